// round 2
// baseline (speedup 1.0000x reference)
#include <cuda_runtime.h>

// CBOW negative-sampling loss, fully fused single-launch.
// Shapes (fixed): B=16384, C=10, K=8, D=128, VOCAB=100000.
// d_in: contexts[B,C] i32, focus_word[B,K] i32, weight_mask[B,K] f32,
//       labels[B,K] f32, ctx_emb[V,D] f32, neg_emb[V,D] f32.
// d_out: 1 float (batch-mean loss).

#define B_N 16384
#define C_N 10
#define K_N 8
#define D_N 128
#define WARPS_PER_BLOCK 16
#define THREADS (WARPS_PER_BLOCK * 32)
#define NBLOCKS (B_N / WARPS_PER_BLOCK)   // 1024

__device__ float        g_partials[NBLOCKS];
__device__ unsigned int g_count;          // zero-initialized; self-resetting

__global__ __launch_bounds__(THREADS)
void cbow_loss_kernel(const int*   __restrict__ contexts,
                      const int*   __restrict__ focus,
                      const float* __restrict__ wmask,
                      const float* __restrict__ labels,
                      const float* __restrict__ ctx_emb,
                      const float* __restrict__ neg_emb,
                      float*       __restrict__ out)
{
    const int warp = threadIdx.x >> 5;
    const int lane = threadIdx.x & 31;
    const int b    = blockIdx.x * WARPS_PER_BLOCK + warp;

    // ---- gather indices (broadcast loads; L1/L2 resident after first touch) ----
    int cidx[C_N];
#pragma unroll
    for (int c = 0; c < C_N; c++) cidx[c] = __ldg(&contexts[b * C_N + c]);

    int fidx[K_N];
#pragma unroll
    for (int k = 0; k < K_N; k++) fidx[k] = __ldg(&focus[b * K_N + k]);

    // ---- sum-pool 10 context rows; lane owns 4 contiguous columns ----
    float4 src = make_float4(0.f, 0.f, 0.f, 0.f);
#pragma unroll
    for (int c = 0; c < C_N; c++) {
        const float4 v =
            __ldg(reinterpret_cast<const float4*>(ctx_emb + (size_t)cidx[c] * D_N) + lane);
        src.x += v.x; src.y += v.y; src.z += v.z; src.w += v.w;
    }

    // ---- 8 target dots (independent LDG.128, then butterfly reduce) ----
    float pred[K_N];
#pragma unroll
    for (int k = 0; k < K_N; k++) {
        const float4 t =
            __ldg(reinterpret_cast<const float4*>(neg_emb + (size_t)fidx[k] * D_N) + lane);
        pred[k] = src.x * t.x + src.y * t.y + src.z * t.z + src.w * t.w;
    }
#pragma unroll
    for (int k = 0; k < K_N; k++) {
        float p = pred[k];
#pragma unroll
        for (int off = 16; off; off >>= 1)
            p += __shfl_xor_sync(0xffffffffu, p, off);
        pred[k] = p;
    }

    // ---- weighted BCE-with-logits, per-row renormalization ----
    float s_bce = 0.f, s_w = 0.f;
#pragma unroll
    for (int k = 0; k < K_N; k++) {
        const float w = __ldg(&wmask[b * K_N + k]);
        const float y = __ldg(&labels[b * K_N + k]);
        const float x = pred[k];
        const float lae = fmaxf(x, 0.f) + log1pf(__expf(-fabsf(x)));
        s_bce += w * (lae - x * y);
        s_w   += w;
    }
    const float per_row = s_bce / s_w;

    // ---- deterministic block partial (fixed summation order) ----
    __shared__ float ws[WARPS_PER_BLOCK];
    __shared__ bool  is_last;
    if (lane == 0) ws[warp] = per_row;
    __syncthreads();
    if (threadIdx.x == 0) {
        float s = 0.f;
#pragma unroll
        for (int i = 0; i < WARPS_PER_BLOCK; i++) s += ws[i];
        g_partials[blockIdx.x] = s;
        __threadfence();                         // partial visible before count bump
        const unsigned prev = atomicAdd(&g_count, 1u);
        is_last = (prev == NBLOCKS - 1u);
    }
    __syncthreads();

    // ---- last block: deterministic final reduction + counter reset ----
    if (is_last) {
        const int tid = threadIdx.x;             // 512 threads
        // fixed-order partial sums: thread i owns positions i, i+512
        float v = g_partials[tid] + g_partials[tid + THREADS];
#pragma unroll
        for (int off = 16; off; off >>= 1)
            v += __shfl_xor_sync(0xffffffffu, v, off);

        __shared__ float s2[WARPS_PER_BLOCK];
        if (lane == 0) s2[tid >> 5] = v;
        __syncthreads();
        if (tid < 32) {
            float x = (tid < WARPS_PER_BLOCK) ? s2[tid] : 0.f;
#pragma unroll
            for (int off = 8; off; off >>= 1)
                x += __shfl_xor_sync(0xffffffffu, x, off);
            if (tid == 0) {
                out[0]  = x * (1.0f / (float)B_N);
                g_count = 0u;                    // reset for next graph replay
            }
        }
    }
}

extern "C" void kernel_launch(void* const* d_in, const int* in_sizes, int n_in,
                              void* d_out, int out_size)
{
    const int*   contexts = (const int*)  d_in[0];
    const int*   focus    = (const int*)  d_in[1];
    const float* wmask    = (const float*)d_in[2];
    const float* labels   = (const float*)d_in[3];
    const float* ctx_emb  = (const float*)d_in[4];
    const float* neg_emb  = (const float*)d_in[5];
    float*       out      = (float*)d_out;

    cbow_loss_kernel<<<NBLOCKS, THREADS>>>(contexts, focus, wmask, labels,
                                           ctx_emb, neg_emb, out);
}

// round 3
// speedup vs baseline: 1.0183x; 1.0183x over previous
#include <cuda_runtime.h>

// CBOW negative-sampling loss, fully fused single-launch.
// Shapes (fixed): B=16384, C=10, K=8, D=128, VOCAB=100000.
// d_in: contexts[B,C] i32, focus_word[B,K] i32, weight_mask[B,K] f32,
//       labels[B,K] f32, ctx_emb[V,D] f32, neg_emb[V,D] f32.
// d_out: 1 float (batch-mean loss).

#define B_N 16384
#define C_N 10
#define K_N 8
#define D_N 128
#define WARPS_PER_BLOCK 8
#define THREADS (WARPS_PER_BLOCK * 32)      // 256
#define NBLOCKS (B_N / WARPS_PER_BLOCK)     // 2048

__device__ float        g_partials[NBLOCKS];
__device__ unsigned int g_count;            // zero-init; self-resetting each run

__global__ __launch_bounds__(THREADS)
void cbow_loss_kernel(const int*   __restrict__ contexts,
                      const int*   __restrict__ focus,
                      const float* __restrict__ wmask,
                      const float* __restrict__ labels,
                      const float* __restrict__ ctx_emb,
                      const float* __restrict__ neg_emb,
                      float*       __restrict__ out)
{
    const int warp = threadIdx.x >> 5;
    const int lane = threadIdx.x & 31;
    const int b    = blockIdx.x * WARPS_PER_BLOCK + warp;

    // ---- gather indices (warp-uniform broadcast loads) ----
    int cidx[C_N];
#pragma unroll
    for (int c = 0; c < C_N; c++) cidx[c] = __ldg(&contexts[b * C_N + c]);

    int fidx[K_N];
#pragma unroll
    for (int k = 0; k < K_N; k++) fidx[k] = __ldg(&focus[b * K_N + k]);

    // ---- sum-pool 10 context rows; lane owns 4 contiguous columns ----
    // 10 independent LDG.128 -> high per-warp MLP.
    float4 src = make_float4(0.f, 0.f, 0.f, 0.f);
#pragma unroll
    for (int c = 0; c < C_N; c++) {
        const float4 v =
            __ldg(reinterpret_cast<const float4*>(ctx_emb + (size_t)cidx[c] * D_N) + lane);
        src.x += v.x; src.y += v.y; src.z += v.z; src.w += v.w;
    }

    // ---- 8 target dots (independent LDG.128, then butterfly reduce) ----
    float pred[K_N];
#pragma unroll
    for (int k = 0; k < K_N; k++) {
        const float4 t =
            __ldg(reinterpret_cast<const float4*>(neg_emb + (size_t)fidx[k] * D_N) + lane);
        pred[k] = src.x * t.x + src.y * t.y + src.z * t.z + src.w * t.w;
    }
#pragma unroll
    for (int k = 0; k < K_N; k++) {
        float p = pred[k];
#pragma unroll
        for (int off = 16; off; off >>= 1)
            p += __shfl_xor_sync(0xffffffffu, p, off);
        pred[k] = p;
    }

    // ---- weighted BCE-with-logits, per-row renormalization ----
    float s_bce = 0.f, s_w = 0.f;
#pragma unroll
    for (int k = 0; k < K_N; k++) {
        const float w = __ldg(&wmask[b * K_N + k]);
        const float y = __ldg(&labels[b * K_N + k]);
        const float x = pred[k];
        const float lae = fmaxf(x, 0.f) + log1pf(__expf(-fabsf(x)));
        s_bce += w * (lae - x * y);
        s_w   += w;
    }
    const float per_row = s_bce / s_w;

    // ---- deterministic block partial (fixed summation order) ----
    __shared__ float ws[WARPS_PER_BLOCK];
    __shared__ bool  is_last;
    if (lane == 0) ws[warp] = per_row;
    __syncthreads();
    if (threadIdx.x == 0) {
        float s = 0.f;
#pragma unroll
        for (int i = 0; i < WARPS_PER_BLOCK; i++) s += ws[i];
        g_partials[blockIdx.x] = s;
        // Publish with release semantics (no full threadfence / L1 flush).
        unsigned prev;
        asm volatile("atom.acq_rel.gpu.global.add.u32 %0, [%1], %2;"
                     : "=r"(prev)
                     : "l"(&g_count), "r"(1u)
                     : "memory");
        is_last = (prev == (unsigned)(NBLOCKS - 1));
    }
    __syncthreads();

    // ---- last block: deterministic final reduction + counter reset ----
    if (is_last) {
        const int tid = threadIdx.x;            // 256 threads, 2048 partials
        float v = 0.f;
#pragma unroll
        for (int j = 0; j < NBLOCKS / THREADS; j++)      // fixed order: 8 chunks
            v += __ldcg(&g_partials[tid + j * THREADS]); // L2 reads, skip stale L1
#pragma unroll
        for (int off = 16; off; off >>= 1)
            v += __shfl_xor_sync(0xffffffffu, v, off);

        __shared__ float s2[WARPS_PER_BLOCK];
        if (lane == 0) s2[tid >> 5] = v;
        __syncthreads();
        if (tid < 32) {
            float x = (tid < WARPS_PER_BLOCK) ? s2[tid] : 0.f;
#pragma unroll
            for (int off = 4; off; off >>= 1)
                x += __shfl_xor_sync(0xffffffffu, x, off);
            if (tid == 0) {
                out[0]  = x * (1.0f / (float)B_N);
                g_count = 0u;                   // reset for next graph replay
            }
        }
    }
}

extern "C" void kernel_launch(void* const* d_in, const int* in_sizes, int n_in,
                              void* d_out, int out_size)
{
    const int*   contexts = (const int*)  d_in[0];
    const int*   focus    = (const int*)  d_in[1];
    const float* wmask    = (const float*)d_in[2];
    const float* labels   = (const float*)d_in[3];
    const float* ctx_emb  = (const float*)d_in[4];
    const float* neg_emb  = (const float*)d_in[5];
    float*       out      = (float*)d_out;

    cbow_loss_kernel<<<NBLOCKS, THREADS>>>(contexts, focus, wmask, labels,
                                           ctx_emb, neg_emb, out);
}

// round 4
// speedup vs baseline: 1.2351x; 1.2129x over previous
#include <cuda_runtime.h>

// CBOW negative-sampling loss, fully fused single-launch.
// Shapes (fixed): B=16384, C=10, K=8, D=128, VOCAB=100000.
// d_in: contexts[B,C] i32, focus_word[B,K] i32, weight_mask[B,K] f32,
//       labels[B,K] f32, ctx_emb[V,D] f32, neg_emb[V,D] f32.
// d_out: 1 float (batch-mean loss).

#define B_N 16384
#define C_N 10
#define K_N 8
#define D_N 128
#define WARPS_PER_BLOCK 8
#define THREADS (WARPS_PER_BLOCK * 32)      // 256
#define NBLOCKS (B_N / WARPS_PER_BLOCK)     // 2048

__device__ float        g_partials[NBLOCKS];
__device__ unsigned int g_count;            // zero-init; self-resetting each run

__global__ __launch_bounds__(THREADS, 8)    // force regs<=32 -> 64 warps/SM
void cbow_loss_kernel(const int*   __restrict__ contexts,
                      const int*   __restrict__ focus,
                      const float* __restrict__ wmask,
                      const float* __restrict__ labels,
                      const float* __restrict__ ctx_emb,
                      const float* __restrict__ neg_emb,
                      float*       __restrict__ out)
{
    const int warp = threadIdx.x >> 5;
    const int lane = threadIdx.x & 31;
    const int b    = blockIdx.x * WARPS_PER_BLOCK + warp;
    const unsigned FULL = 0xffffffffu;

    // ---- gather indices (warp-uniform broadcast loads) ----
    int cidx[C_N];
#pragma unroll
    for (int c = 0; c < C_N; c++) cidx[c] = __ldg(&contexts[b * C_N + c]);

    // focus row is 32B-aligned: 2x int4
    const int4 f0 = __ldg(reinterpret_cast<const int4*>(focus + b * K_N));
    const int4 f1 = __ldg(reinterpret_cast<const int4*>(focus + b * K_N) + 1);
    const int fidx[K_N] = {f0.x, f0.y, f0.z, f0.w, f1.x, f1.y, f1.z, f1.w};

    // ---- sum-pool 10 context rows; lane owns 4 contiguous columns ----
    float4 src = make_float4(0.f, 0.f, 0.f, 0.f);
#pragma unroll
    for (int c = 0; c < C_N; c++) {
        const float4 v =
            __ldg(reinterpret_cast<const float4*>(ctx_emb + (size_t)cidx[c] * D_N) + lane);
        src.x += v.x; src.y += v.y; src.z += v.z; src.w += v.w;
    }

    // ---- 8 per-lane partial dots (independent LDG.128) ----
    float pred[K_N];
#pragma unroll
    for (int k = 0; k < K_N; k++) {
        const float4 t =
            __ldg(reinterpret_cast<const float4*>(neg_emb + (size_t)fidx[k] * D_N) + lane);
        pred[k] = src.x * t.x + src.y * t.y + src.z * t.z + src.w * t.w;
    }

    // ---- packed multi-reduce: 8 reductions in 9 shuffles ----
    // Round 1 (off 16): pair (2j, 2j+1); lane bit4 selects which pred it carries.
    float c4[4];
#pragma unroll
    for (int j = 0; j < 4; j++) {
        const bool lo = (lane & 16) == 0;
        const float keep = lo ? pred[2 * j] : pred[2 * j + 1];
        const float send = lo ? pred[2 * j + 1] : pred[2 * j];
        c4[j] = keep + __shfl_xor_sync(FULL, send, 16);
    }
    // Round 2 (off 8): lane bit3 -> pred bit1.
    float e2[2];
#pragma unroll
    for (int j = 0; j < 2; j++) {
        const bool lo = (lane & 8) == 0;
        const float keep = lo ? c4[2 * j] : c4[2 * j + 1];
        const float send = lo ? c4[2 * j + 1] : c4[2 * j];
        e2[j] = keep + __shfl_xor_sync(FULL, send, 8);
    }
    // Round 3 (off 4): lane bit2 -> pred bit2.
    float f;
    {
        const bool lo = (lane & 4) == 0;
        const float keep = lo ? e2[0] : e2[1];
        const float send = lo ? e2[1] : e2[0];
        f = keep + __shfl_xor_sync(FULL, send, 4);
    }
    // Rounds 4-5: finish within each 4-lane group.
    f += __shfl_xor_sync(FULL, f, 2);
    f += __shfl_xor_sync(FULL, f, 1);
    // Lane now holds the complete dot for pred index:
    const int k = ((lane >> 4) & 1) | (((lane >> 3) & 1) << 1) | (((lane >> 2) & 1) << 2);

    // ---- per-lane weighted BCE term (each k duplicated on 4 lanes) ----
    const float w = __ldg(&wmask[b * K_N + k]);
    const float y = __ldg(&labels[b * K_N + k]);
    const float x = f;
    const float lae = fmaxf(x, 0.f) + log1pf(__expf(-fabsf(x)));
    const float bce = w * (lae - x * y);

    // ---- packed pair-reduce: sum(bce) in lower half, sum(w) in upper ----
    // 4x duplication cancels in the ratio bce/w.
    float r;
    {
        const bool lo = lane < 16;
        const float keep = lo ? bce : w;
        const float send = lo ? w : bce;
        r = keep + __shfl_xor_sync(FULL, send, 16);
    }
    r += __shfl_xor_sync(FULL, r, 8);
    r += __shfl_xor_sync(FULL, r, 4);
    r += __shfl_xor_sync(FULL, r, 2);
    r += __shfl_xor_sync(FULL, r, 1);
    const float wtot = __shfl_sync(FULL, r, 16);   // lane16 holds sum(w)*4

    // ---- deterministic block partial ----
    __shared__ float ws[WARPS_PER_BLOCK];
    __shared__ bool  is_last;
    if (lane == 0) ws[warp] = r / wtot;            // per-row loss
    __syncthreads();
    if (threadIdx.x == 0) {
        float s = 0.f;
#pragma unroll
        for (int i = 0; i < WARPS_PER_BLOCK; i++) s += ws[i];
        g_partials[blockIdx.x] = s;
        unsigned prev;
        asm volatile("atom.acq_rel.gpu.global.add.u32 %0, [%1], %2;"
                     : "=r"(prev)
                     : "l"(&g_count), "r"(1u)
                     : "memory");
        is_last = (prev == (unsigned)(NBLOCKS - 1));
    }
    __syncthreads();

    // ---- last block: deterministic final reduction + counter reset ----
    if (is_last) {
        const int tid = threadIdx.x;               // 256 threads, 2048 partials
        float v = 0.f;
#pragma unroll
        for (int j = 0; j < NBLOCKS / THREADS; j++)
            v += __ldcg(&g_partials[tid + j * THREADS]);
#pragma unroll
        for (int off = 16; off; off >>= 1)
            v += __shfl_xor_sync(FULL, v, off);

        __shared__ float s2[WARPS_PER_BLOCK];
        if (lane == 0) s2[tid >> 5] = v;
        __syncthreads();
        if (tid < 32) {
            float z = (tid < WARPS_PER_BLOCK) ? s2[tid] : 0.f;
#pragma unroll
            for (int off = 4; off; off >>= 1)
                z += __shfl_xor_sync(FULL, z, off);
            if (tid == 0) {
                out[0]  = z * (1.0f / (float)B_N);
                g_count = 0u;                      // reset for next graph replay
            }
        }
    }
}

extern "C" void kernel_launch(void* const* d_in, const int* in_sizes, int n_in,
                              void* d_out, int out_size)
{
    const int*   contexts = (const int*)  d_in[0];
    const int*   focus    = (const int*)  d_in[1];
    const float* wmask    = (const float*)d_in[2];
    const float* labels   = (const float*)d_in[3];
    const float* ctx_emb  = (const float*)d_in[4];
    const float* neg_emb  = (const float*)d_in[5];
    float*       out      = (float*)d_out;

    cbow_loss_kernel<<<NBLOCKS, THREADS>>>(contexts, focus, wmask, labels,
                                           ctx_emb, neg_emb, out);
}